// round 13
// baseline (speedup 1.0000x reference)
#include <cuda_runtime.h>
#include <cuda_fp16.h>
#include <cstdint>

// Problem constants
#define BB 4
#define SS 2048
#define EE 1024
#define HH 16
#define DD 64
#define MROWS (BB * SS)      // 8192
#define QKVN  (3 * HH * DD)  // 3072
#define PITCH 72             // SMEM row pitch in halves (144B, conflict-free)

// Scratch (allocation-free rule: __device__ globals)
__device__ __half g_qkv[(size_t)MROWS * QKVN];  // 48 MB
__device__ __half g_z[(size_t)MROWS * EE];      // 16 MB (scrambled z)
__device__ __half g_xh[(size_t)MROWS * EE];     // 16 MB (x fp16)
__device__ __half g_wqt[(size_t)QKVN * EE];     //  6 MB (W_qkv^T fp16 [N,K])
__device__ __half g_wot[(size_t)EE * EE];       //  2 MB (W_out^T fp16 [N,K])

__device__ __forceinline__ uint32_t h2pack(float lo, float hi) {
    uint32_t r;
    asm("cvt.rn.f16x2.f32 %0, %1, %2;" : "=r"(r) : "f"(hi), "f"(lo));
    return r;
}
__device__ __forceinline__ uint32_t ex2h2(uint32_t x) {
    uint32_t y;
    asm("ex2.approx.f16x2 %0, %1;" : "=r"(y) : "r"(x));
    return y;
}
__device__ __forceinline__ uint32_t sptr(const void* p) {
    return (uint32_t)__cvta_generic_to_shared(p);
}
__device__ __forceinline__ void cp16(void* dst, const void* src) {
    uint32_t d = sptr(dst);
    asm volatile("cp.async.cg.shared.global [%0], [%1], 16;" :: "r"(d), "l"(src));
}
#define CP_COMMIT() asm volatile("cp.async.commit_group;")
#define CP_WAIT0()  asm volatile("cp.async.wait_group 0;")

__device__ __forceinline__ void ldsm4(uint32_t r[4], uint32_t addr) {
    asm volatile("ldmatrix.sync.aligned.m8n8.x4.shared.b16 {%0,%1,%2,%3}, [%4];"
                 : "=r"(r[0]), "=r"(r[1]), "=r"(r[2]), "=r"(r[3]) : "r"(addr));
}
__device__ __forceinline__ void ldsm4t(uint32_t r[4], uint32_t addr) {
    asm volatile("ldmatrix.sync.aligned.m8n8.x4.trans.shared.b16 {%0,%1,%2,%3}, [%4];"
                 : "=r"(r[0]), "=r"(r[1]), "=r"(r[2]), "=r"(r[3]) : "r"(addr));
}
__device__ __forceinline__ void ldsm2t(uint32_t& r0, uint32_t& r1,
                                       uint32_t addr) {
    asm volatile("ldmatrix.sync.aligned.m8n8.x2.trans.shared.b16 {%0,%1}, [%2];"
                 : "=r"(r0), "=r"(r1) : "r"(addr));
}
__device__ __forceinline__ void mma16816(float d[4], const uint32_t a[4],
                                         uint32_t b0, uint32_t b1) {
    asm volatile(
        "mma.sync.aligned.m16n8k16.row.col.f32.f16.f16.f32 "
        "{%0,%1,%2,%3}, {%4,%5,%6,%7}, {%8,%9}, {%0,%1,%2,%3};\n"
        : "+f"(d[0]), "+f"(d[1]), "+f"(d[2]), "+f"(d[3])
        : "r"(a[0]), "r"(a[1]), "r"(a[2]), "r"(a[3]), "r"(b0), "r"(b1));
}

// ---------------------------------------------------------------------------
// Pre-pass: fp32 -> fp16 copy (x) and fp32 -> fp16 transpose (weights)
// ---------------------------------------------------------------------------
__global__ void cvt_half_kernel(const float4* __restrict__ src,
                                uint2* __restrict__ dst, int n4) {
    int i = blockIdx.x * blockDim.x + threadIdx.x;
    if (i < n4) {
        float4 v = src[i];
        uint2 o;
        o.x = h2pack(v.x, v.y);
        o.y = h2pack(v.z, v.w);
        dst[i] = o;
    }
}
__global__ void cvtT_kernel(const float* __restrict__ src,
                            __half* __restrict__ dst, int R, int C) {
    __shared__ float t[32][33];
    int bx = blockIdx.x, by = blockIdx.y;
    int tx = threadIdx.x, ty = threadIdx.y;
    int x = bx * 32 + tx;
#pragma unroll
    for (int i = 0; i < 4; i++) {
        int y = by * 32 + ty + i * 8;
        t[ty + i * 8][tx] = src[(size_t)y * C + x];
    }
    __syncthreads();
    int xo = by * 32 + tx;
#pragma unroll
    for (int i = 0; i < 4; i++) {
        int yo = bx * 32 + ty + i * 8;
        dst[(size_t)yo * R + xo] = __float2half_rn(t[tx][ty + i * 8]);
    }
}

// ---------------------------------------------------------------------------
// fp16 tensor-core GEMM (exact R10/R11 version): C[M,N] = A[M,K] @ Bt[N,K]^T.
// BM=128, BN=128, BK=64, 256 threads (8 warps 4x2), warp tile 32x64.
// 2-stage cp.async; k-major MMA bursts; prefetch spread across quadrants.
// ---------------------------------------------------------------------------
__global__ __launch_bounds__(256, 2) void hgemm_kernel(
    const __half* __restrict__ A, const __half* __restrict__ Bt,
    void* __restrict__ Cv, int M, int N, int K, int half_out)
{
    extern __shared__ __half smh[];
    const int stA = 128 * PITCH;
    __half* Asm = smh;
    __half* Bsm = smh + 2 * stA;

    const int tid = threadIdx.x;
    const int lane = tid & 31;
    const int wid = tid >> 5;
    const int wm = wid & 3;
    const int wn = wid >> 2;
    const int r = lane >> 2;
    const int cq = lane & 3;
    const int m0 = blockIdx.y * 128;
    const int n0 = blockIdx.x * 128;

    const int a_row_l = ((lane >> 3) & 1) * 8 + (lane & 7);
    const int a_col_l = ((lane >> 4) & 1) * 8;
    const int b_row_l = lane & 7;
    const int b_col_l = (lane >> 3) * 8;

    float acc[2][8][4];
#pragma unroll
    for (int i = 0; i < 2; i++)
#pragma unroll
        for (int j = 0; j < 8; j++)
#pragma unroll
            for (int q = 0; q < 4; q++) acc[i][j][q] = 0.f;

    auto cp_chunk = [&](int buf, int k0, int j) {
        int f = (j & 3) * 256 + tid;
        int row = f >> 3;
        int c = (f & 7) * 8;
        if (j < 4)
            cp16(Asm + buf * stA + row * PITCH + c,
                 A + (size_t)(m0 + row) * K + k0 + c);
        else
            cp16(Bsm + buf * stA + row * PITCH + c,
                 Bt + (size_t)(n0 + row) * K + k0 + c);
    };
    auto load_tile = [&](int buf, int k0) {
#pragma unroll
        for (int j = 0; j < 8; j++) cp_chunk(buf, k0, j);
        CP_COMMIT();
    };

    const int ntiles = K / 64;
    load_tile(0, 0);

    for (int it = 0; it < ntiles; it++) {
        const int cur = it & 1;
        CP_WAIT0();
        __syncthreads();
        const bool pf = (it + 1 < ntiles);
        const int nk0 = (it + 1) * 64;

        __half* Ab = Asm + cur * stA;
        __half* Bb = Bsm + cur * stA;

#pragma unroll
        for (int ksp = 0; ksp < 2; ksp++) {
            uint32_t af[2][2][4];
#pragma unroll
            for (int im = 0; im < 2; im++)
#pragma unroll
                for (int sub = 0; sub < 2; sub++)
                    ldsm4(af[im][sub],
                          sptr(Ab + (wm * 32 + im * 16 + a_row_l) * PITCH +
                               ksp * 32 + sub * 16 + a_col_l));

#pragma unroll
            for (int nh = 0; nh < 2; nh++) {
                uint32_t bf[4][4];
#pragma unroll
                for (int g = 0; g < 4; g++)
                    ldsm4(bf[g],
                          sptr(Bb + (wn * 64 + (nh * 4 + g) * 8 + b_row_l) * PITCH +
                               ksp * 32 + b_col_l));

                if (pf) {
                    cp_chunk(cur ^ 1, nk0, 2 * (ksp * 2 + nh));
                    cp_chunk(cur ^ 1, nk0, 2 * (ksp * 2 + nh) + 1);
                }

#pragma unroll
                for (int sub = 0; sub < 2; sub++)
#pragma unroll
                    for (int im = 0; im < 2; im++)
#pragma unroll
                        for (int g = 0; g < 4; g++)
                            mma16816(acc[im][nh * 4 + g], af[im][sub],
                                     bf[g][2 * sub], bf[g][2 * sub + 1]);
            }
        }
        CP_COMMIT();
    }

    if (half_out) {
        __half* C = (__half*)Cv;
#pragma unroll
        for (int im = 0; im < 2; im++)
#pragma unroll
            for (int nt = 0; nt < 8; nt++) {
                int row = m0 + wm * 32 + im * 16 + r;
                int col = n0 + wn * 64 + nt * 8 + 2 * cq;
                *(uint32_t*)(C + (size_t)row * N + col) =
                    h2pack(acc[im][nt][0], acc[im][nt][1]);
                *(uint32_t*)(C + (size_t)(row + 8) * N + col) =
                    h2pack(acc[im][nt][2], acc[im][nt][3]);
            }
    } else {
        float* C = (float*)Cv;
#pragma unroll
        for (int im = 0; im < 2; im++)
#pragma unroll
            for (int nt = 0; nt < 8; nt++) {
                int row = m0 + wm * 32 + im * 16 + r;
                int col = n0 + wn * 64 + nt * 8 + 2 * cq;
                *(float2*)(C + (size_t)row * N + col) =
                    make_float2(acc[im][nt][0], acc[im][nt][1]);
                *(float2*)(C + (size_t)(row + 8) * N + col) =
                    make_float2(acc[im][nt][2], acc[im][nt][3]);
            }
    }
}

// ---------------------------------------------------------------------------
// Flash attention, R11 shape (256 thr, 128 q-rows) but NO online softmax:
// P = exp2(s - 8) with fixed offset; the 2^-8 factor cancels exactly in the
// ones-column normalization. fp16 MMA, f16x2 ex2, 2-stage cp.async.
// Writes z fp16 in scrambled layout: z[b, h*128+s/16, (s%16)*64+d]
// ---------------------------------------------------------------------------
__global__ __launch_bounds__(256, 2) void attn_kernel(
    const __half* __restrict__ qkv, __half* __restrict__ z)
{
    extern __shared__ __half sma[];
    const int stK = 64 * PITCH;
    __half* Ksm = sma;
    __half* Vsm = sma + 2 * stK;

    const int bh = blockIdx.x;
    const int b = bh >> 4;
    const int h = bh & 15;
    const int s0 = blockIdx.y * 128;
    const int tid = threadIdx.x;
    const int lane = tid & 31;
    const int warp = tid >> 5;
    const int r = lane >> 2;
    const int cq = lane & 3;

    const int k_row_l = ((lane >> 4) & 1) * 8 + (lane & 7);
    const int k_col_l = ((lane >> 3) & 1) * 8;
    const int v_row_l = ((lane >> 3) & 1) * 8 + (lane & 7);
    const int v_col_l = ((lane >> 4) & 1) * 8;

    const __half* base = qkv + (size_t)b * SS * QKVN + h * DD;

    const float QSCALE = 0.125f * 1.44269504088896340736f;
    const float SOFF = 8.0f;   // fixed log2-domain offset (cancels in norm)
    uint32_t qa[4][4];
    {
        const int row0 = s0 + warp * 16 + r;
        const __half* q0 = base + (size_t)row0 * QKVN;
        const __half* q1 = base + (size_t)(row0 + 8) * QKVN;
#pragma unroll
        for (int ks = 0; ks < 4; ks++) {
            float2 f0 = __half22float2(*(const __half2*)(q0 + 16 * ks + 2 * cq));
            float2 f1 = __half22float2(*(const __half2*)(q1 + 16 * ks + 2 * cq));
            float2 f2 = __half22float2(*(const __half2*)(q0 + 16 * ks + 8 + 2 * cq));
            float2 f3 = __half22float2(*(const __half2*)(q1 + 16 * ks + 8 + 2 * cq));
            qa[ks][0] = h2pack(f0.x * QSCALE, f0.y * QSCALE);
            qa[ks][1] = h2pack(f1.x * QSCALE, f1.y * QSCALE);
            qa[ks][2] = h2pack(f2.x * QSCALE, f2.y * QSCALE);
            qa[ks][3] = h2pack(f3.x * QSCALE, f3.y * QSCALE);
        }
    }

    // Ones column for l row-sums: V col 64 = 1.0, cols 65-71 = 0 (both bufs).
    if (tid < 128) {
        int buf = tid >> 6, row = tid & 63;
        uint4 ones = make_uint4(0x00003C00u, 0u, 0u, 0u);
        *(uint4*)(Vsm + buf * stK + row * PITCH + 64) = ones;
    }

    auto load_kv = [&](int buf, int kt) {
#pragma unroll
        for (int i = 0; i < 4; i++) {
            int f = i * 256 + tid;
            int isv = f >> 9;
            int g = f & 511;
            int t = g >> 3;
            int c = (g & 7) * 8;
            const __half* src = base + (size_t)(kt + t) * QKVN +
                                (isv ? 2048 : 1024) + c;
            __half* dst = (isv ? Vsm : Ksm) + buf * stK + t * PITCH + c;
            cp16(dst, src);
        }
        CP_COMMIT();
    };

    // o[0..7]: output cols; o[8]: ones-column accumulator (l in [0],[2])
    float o[9][4];
#pragma unroll
    for (int nt = 0; nt < 9; nt++)
#pragma unroll
        for (int q = 0; q < 4; q++) o[nt][q] = 0.f;

    load_kv(0, 0);

    for (int it = 0; it < SS / 64; it++) {
        const int cur = it & 1;
        CP_WAIT0();
        __syncthreads();
        if (it + 1 < SS / 64) load_kv(cur ^ 1, (it + 1) * 64);

        __half* Kb = Ksm + cur * stK;
        __half* Vb = Vsm + cur * stK;

        // S = Q @ K^T (warp: 16 x 64), scores in log2 domain
        float s[8][4];
#pragma unroll
        for (int nt = 0; nt < 8; nt++)
#pragma unroll
            for (int q = 0; q < 4; q++) s[nt][q] = 0.f;
#pragma unroll
        for (int ks = 0; ks < 4; ks++) {
#pragma unroll
            for (int ntp = 0; ntp < 4; ntp++) {
                uint32_t kb[4];
                uint32_t kd = sptr(Kb + (ntp * 16 + k_row_l) * PITCH +
                                   ks * 16 + k_col_l);
                ldsm4(kb, kd);
                mma16816(s[2 * ntp],     qa[ks], kb[0], kb[1]);
                mma16816(s[2 * ntp + 1], qa[ks], kb[2], kb[3]);
            }
        }

        // P = exp2(s - SOFF) directly in f16x2 (A-fragment layout).
        // No online max: offset is constant, cancels in normalization.
        uint32_t pa[4][4];
#pragma unroll
        for (int ks = 0; ks < 4; ks++) {
            pa[ks][0] = ex2h2(h2pack(s[2 * ks][0] - SOFF, s[2 * ks][1] - SOFF));
            pa[ks][1] = ex2h2(h2pack(s[2 * ks][2] - SOFF, s[2 * ks][3] - SOFF));
            pa[ks][2] = ex2h2(h2pack(s[2 * ks + 1][0] - SOFF,
                                     s[2 * ks + 1][1] - SOFF));
            pa[ks][3] = ex2h2(h2pack(s[2 * ks + 1][2] - SOFF,
                                     s[2 * ks + 1][3] - SOFF));
        }

        // O += P @ V  (+ ones-column row sums into o[8])
#pragma unroll
        for (int ks = 0; ks < 4; ks++) {
            uint32_t w0, w1;
            ldsm2t(w0, w1, sptr(Vb + (ks * 16 + (lane & 15)) * PITCH + 64));
            mma16816(o[8], pa[ks], w0, w1);
#pragma unroll
            for (int dp = 0; dp < 4; dp++) {
                uint32_t vb[4];
                uint32_t vd = sptr(Vb + (ks * 16 + v_row_l) * PITCH +
                                   dp * 16 + v_col_l);
                ldsm4t(vb, vd);
                mma16816(o[2 * dp],     pa[ks], vb[0], vb[1]);
                mma16816(o[2 * dp + 1], pa[ks], vb[2], vb[3]);
            }
        }
    }

    // l lives in the cq==0 lane of each quad (col 64)
    float l0 = __shfl_sync(0xffffffffu, o[8][0], lane & ~3);
    float l1 = __shfl_sync(0xffffffffu, o[8][2], lane & ~3);
    float inv0 = 1.f / l0;
    float inv1 = 1.f / l1;
    int sg0 = s0 + warp * 16 + r;
    int sg1 = sg0 + 8;
    int zr0 = h * 128 + (sg0 >> 4);
    int zr1 = h * 128 + (sg1 >> 4);
    __half* d0 = z + ((size_t)b * SS + zr0) * EE + (sg0 & 15) * 64;
    __half* d1 = z + ((size_t)b * SS + zr1) * EE + (sg1 & 15) * 64;
#pragma unroll
    for (int nt = 0; nt < 8; nt++) {
        int col = nt * 8 + 2 * cq;
        *(uint32_t*)(d0 + col) = h2pack(o[nt][0] * inv0, o[nt][1] * inv0);
        *(uint32_t*)(d1 + col) = h2pack(o[nt][2] * inv1, o[nt][3] * inv1);
    }
}

// ---------------------------------------------------------------------------
extern "C" void kernel_launch(void* const* d_in, const int* in_sizes, int n_in,
                              void* d_out, int out_size)
{
    (void)in_sizes; (void)n_in; (void)out_size;
    const float* x    = (const float*)d_in[0];
    const float* Wqkv = (const float*)d_in[1];
    const float* Wout = (const float*)d_in[2];
    float* out = (float*)d_out;

    void *p_qkv, *p_z, *p_xh, *p_wqt, *p_wot;
    cudaGetSymbolAddress(&p_qkv, g_qkv);
    cudaGetSymbolAddress(&p_z, g_z);
    cudaGetSymbolAddress(&p_xh, g_xh);
    cudaGetSymbolAddress(&p_wqt, g_wqt);
    cudaGetSymbolAddress(&p_wot, g_wot);
    __half* qkv = (__half*)p_qkv;
    __half* zb  = (__half*)p_z;
    __half* xh  = (__half*)p_xh;
    __half* wqt = (__half*)p_wqt;
    __half* wot = (__half*)p_wot;

    const int SMEM_G = 2 * 2 * 128 * PITCH * 2;  // 73728
    const int SMEM_A = 2 * 2 * 64 * PITCH * 2;   // 36864
    cudaFuncSetAttribute(hgemm_kernel,
                         cudaFuncAttributeMaxDynamicSharedMemorySize, SMEM_G);
    cudaFuncSetAttribute(attn_kernel,
                         cudaFuncAttributeMaxDynamicSharedMemorySize, SMEM_A);

    // 0) Pre-pass: x -> fp16; weights -> fp16 transposed [N,K]
    {
        int n4x = MROWS * EE / 4;
        cvt_half_kernel<<<(n4x + 255) / 256, 256>>>((const float4*)x,
                                                    (uint2*)xh, n4x);
        cvtT_kernel<<<dim3(QKVN / 32, EE / 32), dim3(32, 8)>>>(Wqkv, wqt,
                                                               EE, QKVN);
        cvtT_kernel<<<dim3(EE / 32, EE / 32), dim3(32, 8)>>>(Wout, wot,
                                                             EE, EE);
    }
    // 1) QKV projection -> fp16 qkv
    hgemm_kernel<<<dim3(QKVN / 128, MROWS / 128), 256, SMEM_G>>>(
        xh, wqt, qkv, MROWS, QKVN, EE, 1);
    // 2) Attention -> fp16 scrambled z
    attn_kernel<<<dim3(BB * HH, SS / 128), 256, SMEM_A>>>(qkv, zb);
    // 3) Output projection -> fp32 out
    hgemm_kernel<<<dim3(EE / 128, MROWS / 128), 256, SMEM_G>>>(
        zb, wot, out, MROWS, EE, EE, 0);
}

// round 14
// speedup vs baseline: 1.4562x; 1.4562x over previous
#include <cuda_runtime.h>
#include <cuda_fp16.h>
#include <cstdint>

// Problem constants
#define BB 4
#define SS 2048
#define EE 1024
#define HH 16
#define DD 64
#define MROWS (BB * SS)      // 8192
#define QKVN  (3 * HH * DD)  // 3072
#define PITCH 72             // SMEM row pitch in halves (144B, conflict-free)

// Scratch (allocation-free rule: __device__ globals)
__device__ __half g_qkv[(size_t)MROWS * QKVN];  // 48 MB
__device__ __half g_z[(size_t)MROWS * EE];      // 16 MB (scrambled z)
__device__ __half g_xh[(size_t)MROWS * EE];     // 16 MB (x fp16)
__device__ __half g_wqt[(size_t)QKVN * EE];     //  6 MB (W_qkv^T fp16 [N,K])
__device__ __half g_wot[(size_t)EE * EE];       //  2 MB (W_out^T fp16 [N,K])

__device__ __forceinline__ uint32_t h2pack(float lo, float hi) {
    uint32_t r;
    asm("cvt.rn.f16x2.f32 %0, %1, %2;" : "=r"(r) : "f"(hi), "f"(lo));
    return r;
}
__device__ __forceinline__ float ex2(float x) {
    float y;
    asm("ex2.approx.f32 %0, %1;" : "=f"(y) : "f"(x));
    return y;
}
__device__ __forceinline__ uint32_t ex2h2(uint32_t x) {
    uint32_t y;
    asm("ex2.approx.f16x2 %0, %1;" : "=r"(y) : "r"(x));
    return y;
}
__device__ __forceinline__ uint32_t sptr(const void* p) {
    return (uint32_t)__cvta_generic_to_shared(p);
}
__device__ __forceinline__ void cp16(void* dst, const void* src) {
    uint32_t d = sptr(dst);
    asm volatile("cp.async.cg.shared.global [%0], [%1], 16;" :: "r"(d), "l"(src));
}
#define CP_COMMIT() asm volatile("cp.async.commit_group;")
#define CP_WAIT0()  asm volatile("cp.async.wait_group 0;")

__device__ __forceinline__ void ldsm4(uint32_t r[4], uint32_t addr) {
    asm volatile("ldmatrix.sync.aligned.m8n8.x4.shared.b16 {%0,%1,%2,%3}, [%4];"
                 : "=r"(r[0]), "=r"(r[1]), "=r"(r[2]), "=r"(r[3]) : "r"(addr));
}
__device__ __forceinline__ void ldsm4t(uint32_t r[4], uint32_t addr) {
    asm volatile("ldmatrix.sync.aligned.m8n8.x4.trans.shared.b16 {%0,%1,%2,%3}, [%4];"
                 : "=r"(r[0]), "=r"(r[1]), "=r"(r[2]), "=r"(r[3]) : "r"(addr));
}
__device__ __forceinline__ void ldsm2t(uint32_t& r0, uint32_t& r1,
                                       uint32_t addr) {
    asm volatile("ldmatrix.sync.aligned.m8n8.x2.trans.shared.b16 {%0,%1}, [%2];"
                 : "=r"(r0), "=r"(r1) : "r"(addr));
}
__device__ __forceinline__ void mma16816(float d[4], const uint32_t a[4],
                                         uint32_t b0, uint32_t b1) {
    asm volatile(
        "mma.sync.aligned.m16n8k16.row.col.f32.f16.f16.f32 "
        "{%0,%1,%2,%3}, {%4,%5,%6,%7}, {%8,%9}, {%0,%1,%2,%3};\n"
        : "+f"(d[0]), "+f"(d[1]), "+f"(d[2]), "+f"(d[3])
        : "r"(a[0]), "r"(a[1]), "r"(a[2]), "r"(a[3]), "r"(b0), "r"(b1));
}

// ---------------------------------------------------------------------------
// Pre-pass: fp32 -> fp16 copy (x) and fp32 -> fp16 transpose (weights)
// ---------------------------------------------------------------------------
__global__ void cvt_half_kernel(const float4* __restrict__ src,
                                uint2* __restrict__ dst, int n4) {
    int i = blockIdx.x * blockDim.x + threadIdx.x;
    if (i < n4) {
        float4 v = src[i];
        uint2 o;
        o.x = h2pack(v.x, v.y);
        o.y = h2pack(v.z, v.w);
        dst[i] = o;
    }
}
__global__ void cvtT_kernel(const float* __restrict__ src,
                            __half* __restrict__ dst, int R, int C) {
    __shared__ float t[32][33];
    int bx = blockIdx.x, by = blockIdx.y;
    int tx = threadIdx.x, ty = threadIdx.y;
    int x = bx * 32 + tx;
#pragma unroll
    for (int i = 0; i < 4; i++) {
        int y = by * 32 + ty + i * 8;
        t[ty + i * 8][tx] = src[(size_t)y * C + x];
    }
    __syncthreads();
    int xo = by * 32 + tx;
#pragma unroll
    for (int i = 0; i < 4; i++) {
        int yo = bx * 32 + ty + i * 8;
        dst[(size_t)yo * R + xo] = __float2half_rn(t[tx][ty + i * 8]);
    }
}

// ---------------------------------------------------------------------------
// fp16 tensor-core GEMM (exact R10/R11 version): C[M,N] = A[M,K] @ Bt[N,K]^T.
// BM=128, BN=128, BK=64, 256 threads (8 warps 4x2), warp tile 32x64.
// 2-stage cp.async; k-major MMA bursts; prefetch spread across quadrants.
// ---------------------------------------------------------------------------
__global__ __launch_bounds__(256, 2) void hgemm_kernel(
    const __half* __restrict__ A, const __half* __restrict__ Bt,
    void* __restrict__ Cv, int M, int N, int K, int half_out)
{
    extern __shared__ __half smh[];
    const int stA = 128 * PITCH;
    __half* Asm = smh;
    __half* Bsm = smh + 2 * stA;

    const int tid = threadIdx.x;
    const int lane = tid & 31;
    const int wid = tid >> 5;
    const int wm = wid & 3;
    const int wn = wid >> 2;
    const int r = lane >> 2;
    const int cq = lane & 3;
    const int m0 = blockIdx.y * 128;
    const int n0 = blockIdx.x * 128;

    const int a_row_l = ((lane >> 3) & 1) * 8 + (lane & 7);
    const int a_col_l = ((lane >> 4) & 1) * 8;
    const int b_row_l = lane & 7;
    const int b_col_l = (lane >> 3) * 8;

    float acc[2][8][4];
#pragma unroll
    for (int i = 0; i < 2; i++)
#pragma unroll
        for (int j = 0; j < 8; j++)
#pragma unroll
            for (int q = 0; q < 4; q++) acc[i][j][q] = 0.f;

    auto cp_chunk = [&](int buf, int k0, int j) {
        int f = (j & 3) * 256 + tid;
        int row = f >> 3;
        int c = (f & 7) * 8;
        if (j < 4)
            cp16(Asm + buf * stA + row * PITCH + c,
                 A + (size_t)(m0 + row) * K + k0 + c);
        else
            cp16(Bsm + buf * stA + row * PITCH + c,
                 Bt + (size_t)(n0 + row) * K + k0 + c);
    };
    auto load_tile = [&](int buf, int k0) {
#pragma unroll
        for (int j = 0; j < 8; j++) cp_chunk(buf, k0, j);
        CP_COMMIT();
    };

    const int ntiles = K / 64;
    load_tile(0, 0);

    for (int it = 0; it < ntiles; it++) {
        const int cur = it & 1;
        CP_WAIT0();
        __syncthreads();
        const bool pf = (it + 1 < ntiles);
        const int nk0 = (it + 1) * 64;

        __half* Ab = Asm + cur * stA;
        __half* Bb = Bsm + cur * stA;

#pragma unroll
        for (int ksp = 0; ksp < 2; ksp++) {
            uint32_t af[2][2][4];
#pragma unroll
            for (int im = 0; im < 2; im++)
#pragma unroll
                for (int sub = 0; sub < 2; sub++)
                    ldsm4(af[im][sub],
                          sptr(Ab + (wm * 32 + im * 16 + a_row_l) * PITCH +
                               ksp * 32 + sub * 16 + a_col_l));

#pragma unroll
            for (int nh = 0; nh < 2; nh++) {
                uint32_t bf[4][4];
#pragma unroll
                for (int g = 0; g < 4; g++)
                    ldsm4(bf[g],
                          sptr(Bb + (wn * 64 + (nh * 4 + g) * 8 + b_row_l) * PITCH +
                               ksp * 32 + b_col_l));

                if (pf) {
                    cp_chunk(cur ^ 1, nk0, 2 * (ksp * 2 + nh));
                    cp_chunk(cur ^ 1, nk0, 2 * (ksp * 2 + nh) + 1);
                }

#pragma unroll
                for (int sub = 0; sub < 2; sub++)
#pragma unroll
                    for (int im = 0; im < 2; im++)
#pragma unroll
                        for (int g = 0; g < 4; g++)
                            mma16816(acc[im][nh * 4 + g], af[im][sub],
                                     bf[g][2 * sub], bf[g][2 * sub + 1]);
            }
        }
        CP_COMMIT();
    }

    if (half_out) {
        __half* C = (__half*)Cv;
#pragma unroll
        for (int im = 0; im < 2; im++)
#pragma unroll
            for (int nt = 0; nt < 8; nt++) {
                int row = m0 + wm * 32 + im * 16 + r;
                int col = n0 + wn * 64 + nt * 8 + 2 * cq;
                *(uint32_t*)(C + (size_t)row * N + col) =
                    h2pack(acc[im][nt][0], acc[im][nt][1]);
                *(uint32_t*)(C + (size_t)(row + 8) * N + col) =
                    h2pack(acc[im][nt][2], acc[im][nt][3]);
            }
    } else {
        float* C = (float*)Cv;
#pragma unroll
        for (int im = 0; im < 2; im++)
#pragma unroll
            for (int nt = 0; nt < 8; nt++) {
                int row = m0 + wm * 32 + im * 16 + r;
                int col = n0 + wn * 64 + nt * 8 + 2 * cq;
                *(float2*)(C + (size_t)row * N + col) =
                    make_float2(acc[im][nt][0], acc[im][nt][1]);
                *(float2*)(C + (size_t)(row + 8) * N + col) =
                    make_float2(acc[im][nt][2], acc[im][nt][3]);
            }
    }
}

// ---------------------------------------------------------------------------
// Flash attention (exact R11 version): fp16 MMA, f16x2 ex2 softmax with
// online max, l via ones-column MMA (V SMEM col 64 = 1.0). 2-stage cp.async.
// grid = (B*H, S/128), 256 threads (8 warps), warp = 16 query rows.
// Writes z fp16 in scrambled layout: z[b, h*128+s/16, (s%16)*64+d]
// ---------------------------------------------------------------------------
__global__ __launch_bounds__(256, 2) void attn_kernel(
    const __half* __restrict__ qkv, __half* __restrict__ z)
{
    extern __shared__ __half sma[];
    const int stK = 64 * PITCH;
    __half* Ksm = sma;
    __half* Vsm = sma + 2 * stK;

    const int bh = blockIdx.x;
    const int b = bh >> 4;
    const int h = bh & 15;
    const int s0 = blockIdx.y * 128;
    const int tid = threadIdx.x;
    const int lane = tid & 31;
    const int warp = tid >> 5;
    const int r = lane >> 2;
    const int cq = lane & 3;

    const int k_row_l = ((lane >> 4) & 1) * 8 + (lane & 7);
    const int k_col_l = ((lane >> 3) & 1) * 8;
    const int v_row_l = ((lane >> 3) & 1) * 8 + (lane & 7);
    const int v_col_l = ((lane >> 4) & 1) * 8;

    const __half* base = qkv + (size_t)b * SS * QKVN + h * DD;

    const float QSCALE = 0.125f * 1.44269504088896340736f;
    uint32_t qa[4][4];
    {
        const int row0 = s0 + warp * 16 + r;
        const __half* q0 = base + (size_t)row0 * QKVN;
        const __half* q1 = base + (size_t)(row0 + 8) * QKVN;
#pragma unroll
        for (int ks = 0; ks < 4; ks++) {
            float2 f0 = __half22float2(*(const __half2*)(q0 + 16 * ks + 2 * cq));
            float2 f1 = __half22float2(*(const __half2*)(q1 + 16 * ks + 2 * cq));
            float2 f2 = __half22float2(*(const __half2*)(q0 + 16 * ks + 8 + 2 * cq));
            float2 f3 = __half22float2(*(const __half2*)(q1 + 16 * ks + 8 + 2 * cq));
            qa[ks][0] = h2pack(f0.x * QSCALE, f0.y * QSCALE);
            qa[ks][1] = h2pack(f1.x * QSCALE, f1.y * QSCALE);
            qa[ks][2] = h2pack(f2.x * QSCALE, f2.y * QSCALE);
            qa[ks][3] = h2pack(f3.x * QSCALE, f3.y * QSCALE);
        }
    }

    // Ones column for l row-sums: V col 64 = 1.0, cols 65-71 = 0 (both bufs).
    if (tid < 128) {
        int buf = tid >> 6, row = tid & 63;
        uint4 ones = make_uint4(0x00003C00u, 0u, 0u, 0u);
        *(uint4*)(Vsm + buf * stK + row * PITCH + 64) = ones;
    }

    auto load_kv = [&](int buf, int kt) {
#pragma unroll
        for (int i = 0; i < 4; i++) {
            int f = i * 256 + tid;
            int isv = f >> 9;
            int g = f & 511;
            int t = g >> 3;
            int c = (g & 7) * 8;
            const __half* src = base + (size_t)(kt + t) * QKVN +
                                (isv ? 2048 : 1024) + c;
            __half* dst = (isv ? Vsm : Ksm) + buf * stK + t * PITCH + c;
            cp16(dst, src);
        }
        CP_COMMIT();
    };

    // o[0..7]: output cols; o[8]: ones-column accumulator (l in [0],[2])
    float o[9][4];
#pragma unroll
    for (int nt = 0; nt < 9; nt++)
#pragma unroll
        for (int q = 0; q < 4; q++) o[nt][q] = 0.f;
    float mrow0 = -1e30f, mrow1 = -1e30f;

    load_kv(0, 0);

    for (int it = 0; it < SS / 64; it++) {
        const int cur = it & 1;
        CP_WAIT0();
        __syncthreads();
        if (it + 1 < SS / 64) load_kv(cur ^ 1, (it + 1) * 64);

        __half* Kb = Ksm + cur * stK;
        __half* Vb = Vsm + cur * stK;

        // S = Q @ K^T (warp: 16 x 64), scores in log2 domain
        float s[8][4];
#pragma unroll
        for (int nt = 0; nt < 8; nt++)
#pragma unroll
            for (int q = 0; q < 4; q++) s[nt][q] = 0.f;
#pragma unroll
        for (int ks = 0; ks < 4; ks++) {
#pragma unroll
            for (int ntp = 0; ntp < 4; ntp++) {
                uint32_t kb[4];
                uint32_t kd = sptr(Kb + (ntp * 16 + k_row_l) * PITCH +
                                   ks * 16 + k_col_l);
                ldsm4(kb, kd);
                mma16816(s[2 * ntp],     qa[ks], kb[0], kb[1]);
                mma16816(s[2 * ntp + 1], qa[ks], kb[2], kb[3]);
            }
        }

        // Online max (base-2 domain)
        float mt0 = -1e30f, mt1 = -1e30f;
#pragma unroll
        for (int nt = 0; nt < 8; nt++) {
            mt0 = fmaxf(mt0, fmaxf(s[nt][0], s[nt][1]));
            mt1 = fmaxf(mt1, fmaxf(s[nt][2], s[nt][3]));
        }
        mt0 = fmaxf(mt0, __shfl_xor_sync(0xffffffffu, mt0, 1));
        mt0 = fmaxf(mt0, __shfl_xor_sync(0xffffffffu, mt0, 2));
        mt1 = fmaxf(mt1, __shfl_xor_sync(0xffffffffu, mt1, 1));
        mt1 = fmaxf(mt1, __shfl_xor_sync(0xffffffffu, mt1, 2));
        float mn0 = fmaxf(mrow0, mt0);
        float mn1 = fmaxf(mrow1, mt1);
        float corr0 = ex2(mrow0 - mn0);
        float corr1 = ex2(mrow1 - mn1);
        mrow0 = mn0;
        mrow1 = mn1;

        // P = exp2(s - mn) directly in f16x2 (A-fragment layout)
        uint32_t pa[4][4];
#pragma unroll
        for (int ks = 0; ks < 4; ks++) {
            pa[ks][0] = ex2h2(h2pack(s[2 * ks][0] - mn0, s[2 * ks][1] - mn0));
            pa[ks][1] = ex2h2(h2pack(s[2 * ks][2] - mn1, s[2 * ks][3] - mn1));
            pa[ks][2] = ex2h2(h2pack(s[2 * ks + 1][0] - mn0,
                                     s[2 * ks + 1][1] - mn0));
            pa[ks][3] = ex2h2(h2pack(s[2 * ks + 1][2] - mn1,
                                     s[2 * ks + 1][3] - mn1));
        }

        // Rescale all accumulators (incl. ones column)
#pragma unroll
        for (int nt = 0; nt < 9; nt++) {
            o[nt][0] *= corr0;
            o[nt][1] *= corr0;
            o[nt][2] *= corr1;
            o[nt][3] *= corr1;
        }

        // O += P @ V  (+ ones-column row sums into o[8])
#pragma unroll
        for (int ks = 0; ks < 4; ks++) {
            uint32_t w0, w1;
            ldsm2t(w0, w1, sptr(Vb + (ks * 16 + (lane & 15)) * PITCH + 64));
            mma16816(o[8], pa[ks], w0, w1);
#pragma unroll
            for (int dp = 0; dp < 4; dp++) {
                uint32_t vb[4];
                uint32_t vd = sptr(Vb + (ks * 16 + v_row_l) * PITCH +
                                   dp * 16 + v_col_l);
                ldsm4t(vb, vd);
                mma16816(o[2 * dp],     pa[ks], vb[0], vb[1]);
                mma16816(o[2 * dp + 1], pa[ks], vb[2], vb[3]);
            }
        }
    }

    // l lives in the cq==0 lane of each quad (col 64)
    float l0 = __shfl_sync(0xffffffffu, o[8][0], lane & ~3);
    float l1 = __shfl_sync(0xffffffffu, o[8][2], lane & ~3);
    float inv0 = 1.f / l0;
    float inv1 = 1.f / l1;
    int sg0 = s0 + warp * 16 + r;
    int sg1 = sg0 + 8;
    int zr0 = h * 128 + (sg0 >> 4);
    int zr1 = h * 128 + (sg1 >> 4);
    __half* d0 = z + ((size_t)b * SS + zr0) * EE + (sg0 & 15) * 64;
    __half* d1 = z + ((size_t)b * SS + zr1) * EE + (sg1 & 15) * 64;
#pragma unroll
    for (int nt = 0; nt < 8; nt++) {
        int col = nt * 8 + 2 * cq;
        *(uint32_t*)(d0 + col) = h2pack(o[nt][0] * inv0, o[nt][1] * inv0);
        *(uint32_t*)(d1 + col) = h2pack(o[nt][2] * inv1, o[nt][3] * inv1);
    }
}

// ---------------------------------------------------------------------------
extern "C" void kernel_launch(void* const* d_in, const int* in_sizes, int n_in,
                              void* d_out, int out_size)
{
    (void)in_sizes; (void)n_in; (void)out_size;
    const float* x    = (const float*)d_in[0];
    const float* Wqkv = (const float*)d_in[1];
    const float* Wout = (const float*)d_in[2];
    float* out = (float*)d_out;

    void *p_qkv, *p_z, *p_xh, *p_wqt, *p_wot;
    cudaGetSymbolAddress(&p_qkv, g_qkv);
    cudaGetSymbolAddress(&p_z, g_z);
    cudaGetSymbolAddress(&p_xh, g_xh);
    cudaGetSymbolAddress(&p_wqt, g_wqt);
    cudaGetSymbolAddress(&p_wot, g_wot);
    __half* qkv = (__half*)p_qkv;
    __half* zb  = (__half*)p_z;
    __half* xh  = (__half*)p_xh;
    __half* wqt = (__half*)p_wqt;
    __half* wot = (__half*)p_wot;

    const int SMEM_G = 2 * 2 * 128 * PITCH * 2;  // 73728
    const int SMEM_A = 2 * 2 * 64 * PITCH * 2;   // 36864
    cudaFuncSetAttribute(hgemm_kernel,
                         cudaFuncAttributeMaxDynamicSharedMemorySize, SMEM_G);
    cudaFuncSetAttribute(attn_kernel,
                         cudaFuncAttributeMaxDynamicSharedMemorySize, SMEM_A);

    dim3 blk(256);
    // 0) Pre-pass: x -> fp16; weights -> fp16 transposed [N,K]
    {
        int n4x = MROWS * EE / 4;
        cvt_half_kernel<<<(n4x + 255) / 256, blk>>>((const float4*)x,
                                                    (uint2*)xh, n4x);
        cvtT_kernel<<<dim3(QKVN / 32, EE / 32), dim3(32, 8)>>>(Wqkv, wqt,
                                                               EE, QKVN);
        cvtT_kernel<<<dim3(EE / 32, EE / 32), dim3(32, 8)>>>(Wout, wot,
                                                             EE, EE);
    }
    // 1) QKV projection -> fp16 qkv
    hgemm_kernel<<<dim3(QKVN / 128, MROWS / 128), blk, SMEM_G>>>(
        xh, wqt, qkv, MROWS, QKVN, EE, 1);
    // 2) Attention -> fp16 scrambled z
    attn_kernel<<<dim3(BB * HH, SS / 128), blk, SMEM_A>>>(qkv, zb);
    // 3) Output projection -> fp32 out
    hgemm_kernel<<<dim3(EE / 128, MROWS / 128), blk, SMEM_G>>>(
        zb, wot, out, MROWS, EE, EE, 0);
}

// round 15
// speedup vs baseline: 1.4709x; 1.0100x over previous
#include <cuda_runtime.h>
#include <cuda_fp16.h>
#include <cstdint>

// Problem constants
#define BB 4
#define SS 2048
#define EE 1024
#define HH 16
#define DD 64
#define MROWS (BB * SS)      // 8192
#define QKVN  (3 * HH * DD)  // 3072
#define PITCH 72             // SMEM row pitch in halves (144B, conflict-free)

// Scratch (allocation-free rule: __device__ globals)
__device__ __half g_qkv[(size_t)MROWS * QKVN];  // 48 MB
__device__ __half g_z[(size_t)MROWS * EE];      // 16 MB (scrambled z)
__device__ __half g_xh[(size_t)MROWS * EE];     // 16 MB (x fp16)
__device__ __half g_wqt[(size_t)QKVN * EE];     //  6 MB (W_qkv^T fp16 [N,K])
__device__ __half g_wot[(size_t)EE * EE];       //  2 MB (W_out^T fp16 [N,K])

__device__ __forceinline__ uint32_t h2pack(float lo, float hi) {
    uint32_t r;
    asm("cvt.rn.f16x2.f32 %0, %1, %2;" : "=r"(r) : "f"(hi), "f"(lo));
    return r;
}
__device__ __forceinline__ float ex2(float x) {
    float y;
    asm("ex2.approx.f32 %0, %1;" : "=f"(y) : "f"(x));
    return y;
}
__device__ __forceinline__ uint32_t ex2h2(uint32_t x) {
    uint32_t y;
    asm("ex2.approx.f16x2 %0, %1;" : "=r"(y) : "r"(x));
    return y;
}
__device__ __forceinline__ uint32_t sptr(const void* p) {
    return (uint32_t)__cvta_generic_to_shared(p);
}
__device__ __forceinline__ void cp16(void* dst, const void* src) {
    uint32_t d = sptr(dst);
    asm volatile("cp.async.cg.shared.global [%0], [%1], 16;" :: "r"(d), "l"(src));
}
#define CP_COMMIT() asm volatile("cp.async.commit_group;")
#define CP_WAIT0()  asm volatile("cp.async.wait_group 0;")

__device__ __forceinline__ void ldsm4(uint32_t r[4], uint32_t addr) {
    asm volatile("ldmatrix.sync.aligned.m8n8.x4.shared.b16 {%0,%1,%2,%3}, [%4];"
                 : "=r"(r[0]), "=r"(r[1]), "=r"(r[2]), "=r"(r[3]) : "r"(addr));
}
__device__ __forceinline__ void ldsm4t(uint32_t r[4], uint32_t addr) {
    asm volatile("ldmatrix.sync.aligned.m8n8.x4.trans.shared.b16 {%0,%1,%2,%3}, [%4];"
                 : "=r"(r[0]), "=r"(r[1]), "=r"(r[2]), "=r"(r[3]) : "r"(addr));
}
__device__ __forceinline__ void ldsm2t(uint32_t& r0, uint32_t& r1,
                                       uint32_t addr) {
    asm volatile("ldmatrix.sync.aligned.m8n8.x2.trans.shared.b16 {%0,%1}, [%2];"
                 : "=r"(r0), "=r"(r1) : "r"(addr));
}
__device__ __forceinline__ void mma16816(float d[4], const uint32_t a[4],
                                         uint32_t b0, uint32_t b1) {
    asm volatile(
        "mma.sync.aligned.m16n8k16.row.col.f32.f16.f16.f32 "
        "{%0,%1,%2,%3}, {%4,%5,%6,%7}, {%8,%9}, {%0,%1,%2,%3};\n"
        : "+f"(d[0]), "+f"(d[1]), "+f"(d[2]), "+f"(d[3])
        : "r"(a[0]), "r"(a[1]), "r"(a[2]), "r"(a[3]), "r"(b0), "r"(b1));
}

// ---------------------------------------------------------------------------
// Merged pre-pass: one kernel, linear block ranges.
//   [0, NBX)              : x fp32 -> fp16 copy (vectorized)
//   [NBX, NBX+NBQ)        : W_qkv [E, QKVN] -> W_qkv^T fp16 [QKVN, E]
//   [NBX+NBQ, +NBO)       : W_out [E, E]    -> W_out^T fp16 [E, E]
// 256 threads used as (32, 8) for the transpose sections.
// ---------------------------------------------------------------------------
#define NBX (MROWS * EE / 4 / 256)      // 8192
#define NBQ ((QKVN / 32) * (EE / 32))   // 3072
#define NBO ((EE / 32) * (EE / 32))     // 1024

__device__ __forceinline__ void transpose_tile(
    const float* __restrict__ src, __half* __restrict__ dst,
    int R, int C, int bx, int by, int tx, int ty, float* t /*[32][33]*/)
{
    int x = bx * 32 + tx;
#pragma unroll
    for (int i = 0; i < 4; i++) {
        int y = by * 32 + ty + i * 8;
        t[(ty + i * 8) * 33 + tx] = src[(size_t)y * C + x];
    }
    __syncthreads();
    int xo = by * 32 + tx;
#pragma unroll
    for (int i = 0; i < 4; i++) {
        int yo = bx * 32 + ty + i * 8;
        dst[(size_t)yo * R + xo] = __float2half_rn(t[tx * 33 + ty + i * 8]);
    }
}

__global__ __launch_bounds__(256) void prepass_kernel(
    const float* __restrict__ x, const float* __restrict__ Wqkv,
    const float* __restrict__ Wout, __half* __restrict__ xh,
    __half* __restrict__ wqt, __half* __restrict__ wot)
{
    __shared__ float t[32 * 33];
    const int blk = blockIdx.x;
    const int tid = threadIdx.x;
    const int tx = tid & 31;
    const int ty = tid >> 5;

    if (blk < NBX) {
        int i = blk * 256 + tid;
        float4 v = ((const float4*)x)[i];
        uint2 o;
        o.x = h2pack(v.x, v.y);
        o.y = h2pack(v.z, v.w);
        ((uint2*)xh)[i] = o;
    } else if (blk < NBX + NBQ) {
        int idx = blk - NBX;
        int bx = idx % (QKVN / 32);
        int by = idx / (QKVN / 32);
        transpose_tile(Wqkv, wqt, EE, QKVN, bx, by, tx, ty, t);
    } else {
        int idx = blk - NBX - NBQ;
        int bx = idx % (EE / 32);
        int by = idx / (EE / 32);
        transpose_tile(Wout, wot, EE, EE, bx, by, tx, ty, t);
    }
}

// ---------------------------------------------------------------------------
// fp16 tensor-core GEMM (exact R10/R11 version): C[M,N] = A[M,K] @ Bt[N,K]^T.
// BM=128, BN=128, BK=64, 256 threads (8 warps 4x2), warp tile 32x64.
// 2-stage cp.async; k-major MMA bursts; prefetch spread across quadrants.
// ---------------------------------------------------------------------------
__global__ __launch_bounds__(256, 2) void hgemm_kernel(
    const __half* __restrict__ A, const __half* __restrict__ Bt,
    void* __restrict__ Cv, int M, int N, int K, int half_out)
{
    extern __shared__ __half smh[];
    const int stA = 128 * PITCH;
    __half* Asm = smh;
    __half* Bsm = smh + 2 * stA;

    const int tid = threadIdx.x;
    const int lane = tid & 31;
    const int wid = tid >> 5;
    const int wm = wid & 3;
    const int wn = wid >> 2;
    const int r = lane >> 2;
    const int cq = lane & 3;
    const int m0 = blockIdx.y * 128;
    const int n0 = blockIdx.x * 128;

    const int a_row_l = ((lane >> 3) & 1) * 8 + (lane & 7);
    const int a_col_l = ((lane >> 4) & 1) * 8;
    const int b_row_l = lane & 7;
    const int b_col_l = (lane >> 3) * 8;

    float acc[2][8][4];
#pragma unroll
    for (int i = 0; i < 2; i++)
#pragma unroll
        for (int j = 0; j < 8; j++)
#pragma unroll
            for (int q = 0; q < 4; q++) acc[i][j][q] = 0.f;

    auto cp_chunk = [&](int buf, int k0, int j) {
        int f = (j & 3) * 256 + tid;
        int row = f >> 3;
        int c = (f & 7) * 8;
        if (j < 4)
            cp16(Asm + buf * stA + row * PITCH + c,
                 A + (size_t)(m0 + row) * K + k0 + c);
        else
            cp16(Bsm + buf * stA + row * PITCH + c,
                 Bt + (size_t)(n0 + row) * K + k0 + c);
    };
    auto load_tile = [&](int buf, int k0) {
#pragma unroll
        for (int j = 0; j < 8; j++) cp_chunk(buf, k0, j);
        CP_COMMIT();
    };

    const int ntiles = K / 64;
    load_tile(0, 0);

    for (int it = 0; it < ntiles; it++) {
        const int cur = it & 1;
        CP_WAIT0();
        __syncthreads();
        const bool pf = (it + 1 < ntiles);
        const int nk0 = (it + 1) * 64;

        __half* Ab = Asm + cur * stA;
        __half* Bb = Bsm + cur * stA;

#pragma unroll
        for (int ksp = 0; ksp < 2; ksp++) {
            uint32_t af[2][2][4];
#pragma unroll
            for (int im = 0; im < 2; im++)
#pragma unroll
                for (int sub = 0; sub < 2; sub++)
                    ldsm4(af[im][sub],
                          sptr(Ab + (wm * 32 + im * 16 + a_row_l) * PITCH +
                               ksp * 32 + sub * 16 + a_col_l));

#pragma unroll
            for (int nh = 0; nh < 2; nh++) {
                uint32_t bf[4][4];
#pragma unroll
                for (int g = 0; g < 4; g++)
                    ldsm4(bf[g],
                          sptr(Bb + (wn * 64 + (nh * 4 + g) * 8 + b_row_l) * PITCH +
                               ksp * 32 + b_col_l));

                if (pf) {
                    cp_chunk(cur ^ 1, nk0, 2 * (ksp * 2 + nh));
                    cp_chunk(cur ^ 1, nk0, 2 * (ksp * 2 + nh) + 1);
                }

#pragma unroll
                for (int sub = 0; sub < 2; sub++)
#pragma unroll
                    for (int im = 0; im < 2; im++)
#pragma unroll
                        for (int g = 0; g < 4; g++)
                            mma16816(acc[im][nh * 4 + g], af[im][sub],
                                     bf[g][2 * sub], bf[g][2 * sub + 1]);
            }
        }
        CP_COMMIT();
    }

    if (half_out) {
        __half* C = (__half*)Cv;
#pragma unroll
        for (int im = 0; im < 2; im++)
#pragma unroll
            for (int nt = 0; nt < 8; nt++) {
                int row = m0 + wm * 32 + im * 16 + r;
                int col = n0 + wn * 64 + nt * 8 + 2 * cq;
                *(uint32_t*)(C + (size_t)row * N + col) =
                    h2pack(acc[im][nt][0], acc[im][nt][1]);
                *(uint32_t*)(C + (size_t)(row + 8) * N + col) =
                    h2pack(acc[im][nt][2], acc[im][nt][3]);
            }
    } else {
        float* C = (float*)Cv;
#pragma unroll
        for (int im = 0; im < 2; im++)
#pragma unroll
            for (int nt = 0; nt < 8; nt++) {
                int row = m0 + wm * 32 + im * 16 + r;
                int col = n0 + wn * 64 + nt * 8 + 2 * cq;
                *(float2*)(C + (size_t)row * N + col) =
                    make_float2(acc[im][nt][0], acc[im][nt][1]);
                *(float2*)(C + (size_t)(row + 8) * N + col) =
                    make_float2(acc[im][nt][2], acc[im][nt][3]);
            }
    }
}

// ---------------------------------------------------------------------------
// Flash attention (R11 + rescale-skip): fp16 MMA, f16x2 ex2 softmax with
// online max, l via ones-column MMA. Rescale block skipped (bit-exact)
// when no row max changed across the whole warp.
// grid = (B*H, S/128), 256 threads (8 warps), warp = 16 query rows.
// Writes z fp16 in scrambled layout: z[b, h*128+s/16, (s%16)*64+d]
// ---------------------------------------------------------------------------
__global__ __launch_bounds__(256, 2) void attn_kernel(
    const __half* __restrict__ qkv, __half* __restrict__ z)
{
    extern __shared__ __half sma[];
    const int stK = 64 * PITCH;
    __half* Ksm = sma;
    __half* Vsm = sma + 2 * stK;

    const int bh = blockIdx.x;
    const int b = bh >> 4;
    const int h = bh & 15;
    const int s0 = blockIdx.y * 128;
    const int tid = threadIdx.x;
    const int lane = tid & 31;
    const int warp = tid >> 5;
    const int r = lane >> 2;
    const int cq = lane & 3;

    const int k_row_l = ((lane >> 4) & 1) * 8 + (lane & 7);
    const int k_col_l = ((lane >> 3) & 1) * 8;
    const int v_row_l = ((lane >> 3) & 1) * 8 + (lane & 7);
    const int v_col_l = ((lane >> 4) & 1) * 8;

    const __half* base = qkv + (size_t)b * SS * QKVN + h * DD;

    const float QSCALE = 0.125f * 1.44269504088896340736f;
    uint32_t qa[4][4];
    {
        const int row0 = s0 + warp * 16 + r;
        const __half* q0 = base + (size_t)row0 * QKVN;
        const __half* q1 = base + (size_t)(row0 + 8) * QKVN;
#pragma unroll
        for (int ks = 0; ks < 4; ks++) {
            float2 f0 = __half22float2(*(const __half2*)(q0 + 16 * ks + 2 * cq));
            float2 f1 = __half22float2(*(const __half2*)(q1 + 16 * ks + 2 * cq));
            float2 f2 = __half22float2(*(const __half2*)(q0 + 16 * ks + 8 + 2 * cq));
            float2 f3 = __half22float2(*(const __half2*)(q1 + 16 * ks + 8 + 2 * cq));
            qa[ks][0] = h2pack(f0.x * QSCALE, f0.y * QSCALE);
            qa[ks][1] = h2pack(f1.x * QSCALE, f1.y * QSCALE);
            qa[ks][2] = h2pack(f2.x * QSCALE, f2.y * QSCALE);
            qa[ks][3] = h2pack(f3.x * QSCALE, f3.y * QSCALE);
        }
    }

    // Ones column for l row-sums: V col 64 = 1.0, cols 65-71 = 0 (both bufs).
    if (tid < 128) {
        int buf = tid >> 6, row = tid & 63;
        uint4 ones = make_uint4(0x00003C00u, 0u, 0u, 0u);
        *(uint4*)(Vsm + buf * stK + row * PITCH + 64) = ones;
    }

    auto load_kv = [&](int buf, int kt) {
#pragma unroll
        for (int i = 0; i < 4; i++) {
            int f = i * 256 + tid;
            int isv = f >> 9;
            int g = f & 511;
            int t = g >> 3;
            int c = (g & 7) * 8;
            const __half* src = base + (size_t)(kt + t) * QKVN +
                                (isv ? 2048 : 1024) + c;
            __half* dst = (isv ? Vsm : Ksm) + buf * stK + t * PITCH + c;
            cp16(dst, src);
        }
        CP_COMMIT();
    };

    // o[0..7]: output cols; o[8]: ones-column accumulator (l in [0],[2])
    float o[9][4];
#pragma unroll
    for (int nt = 0; nt < 9; nt++)
#pragma unroll
        for (int q = 0; q < 4; q++) o[nt][q] = 0.f;
    float mrow0 = -1e30f, mrow1 = -1e30f;

    load_kv(0, 0);

    for (int it = 0; it < SS / 64; it++) {
        const int cur = it & 1;
        CP_WAIT0();
        __syncthreads();
        if (it + 1 < SS / 64) load_kv(cur ^ 1, (it + 1) * 64);

        __half* Kb = Ksm + cur * stK;
        __half* Vb = Vsm + cur * stK;

        // S = Q @ K^T (warp: 16 x 64), scores in log2 domain
        float s[8][4];
#pragma unroll
        for (int nt = 0; nt < 8; nt++)
#pragma unroll
            for (int q = 0; q < 4; q++) s[nt][q] = 0.f;
#pragma unroll
        for (int ks = 0; ks < 4; ks++) {
#pragma unroll
            for (int ntp = 0; ntp < 4; ntp++) {
                uint32_t kb[4];
                uint32_t kd = sptr(Kb + (ntp * 16 + k_row_l) * PITCH +
                                   ks * 16 + k_col_l);
                ldsm4(kb, kd);
                mma16816(s[2 * ntp],     qa[ks], kb[0], kb[1]);
                mma16816(s[2 * ntp + 1], qa[ks], kb[2], kb[3]);
            }
        }

        // Online max (base-2 domain)
        float mt0 = -1e30f, mt1 = -1e30f;
#pragma unroll
        for (int nt = 0; nt < 8; nt++) {
            mt0 = fmaxf(mt0, fmaxf(s[nt][0], s[nt][1]));
            mt1 = fmaxf(mt1, fmaxf(s[nt][2], s[nt][3]));
        }
        mt0 = fmaxf(mt0, __shfl_xor_sync(0xffffffffu, mt0, 1));
        mt0 = fmaxf(mt0, __shfl_xor_sync(0xffffffffu, mt0, 2));
        mt1 = fmaxf(mt1, __shfl_xor_sync(0xffffffffu, mt1, 1));
        mt1 = fmaxf(mt1, __shfl_xor_sync(0xffffffffu, mt1, 2));
        float mn0 = fmaxf(mrow0, mt0);
        float mn1 = fmaxf(mrow1, mt1);

        // Rescale only if some row max changed anywhere in the warp.
        // When mn==mrow for all lanes, corr==1.0 and the multiply block
        // is an exact no-op -> skipping is bit-identical.
        bool stable = (mn0 == mrow0) && (mn1 == mrow1);
        if (!__all_sync(0xffffffffu, stable)) {
            float corr0 = ex2(mrow0 - mn0);
            float corr1 = ex2(mrow1 - mn1);
#pragma unroll
            for (int nt = 0; nt < 9; nt++) {
                o[nt][0] *= corr0;
                o[nt][1] *= corr0;
                o[nt][2] *= corr1;
                o[nt][3] *= corr1;
            }
        }
        mrow0 = mn0;
        mrow1 = mn1;

        // P = exp2(s - mn) directly in f16x2 (A-fragment layout)
        uint32_t pa[4][4];
#pragma unroll
        for (int ks = 0; ks < 4; ks++) {
            pa[ks][0] = ex2h2(h2pack(s[2 * ks][0] - mn0, s[2 * ks][1] - mn0));
            pa[ks][1] = ex2h2(h2pack(s[2 * ks][2] - mn1, s[2 * ks][3] - mn1));
            pa[ks][2] = ex2h2(h2pack(s[2 * ks + 1][0] - mn0,
                                     s[2 * ks + 1][1] - mn0));
            pa[ks][3] = ex2h2(h2pack(s[2 * ks + 1][2] - mn1,
                                     s[2 * ks + 1][3] - mn1));
        }

        // O += P @ V  (+ ones-column row sums into o[8])
#pragma unroll
        for (int ks = 0; ks < 4; ks++) {
            uint32_t w0, w1;
            ldsm2t(w0, w1, sptr(Vb + (ks * 16 + (lane & 15)) * PITCH + 64));
            mma16816(o[8], pa[ks], w0, w1);
#pragma unroll
            for (int dp = 0; dp < 4; dp++) {
                uint32_t vb[4];
                uint32_t vd = sptr(Vb + (ks * 16 + v_row_l) * PITCH +
                                   dp * 16 + v_col_l);
                ldsm4t(vb, vd);
                mma16816(o[2 * dp],     pa[ks], vb[0], vb[1]);
                mma16816(o[2 * dp + 1], pa[ks], vb[2], vb[3]);
            }
        }
    }

    // l lives in the cq==0 lane of each quad (col 64)
    float l0 = __shfl_sync(0xffffffffu, o[8][0], lane & ~3);
    float l1 = __shfl_sync(0xffffffffu, o[8][2], lane & ~3);
    float inv0 = 1.f / l0;
    float inv1 = 1.f / l1;
    int sg0 = s0 + warp * 16 + r;
    int sg1 = sg0 + 8;
    int zr0 = h * 128 + (sg0 >> 4);
    int zr1 = h * 128 + (sg1 >> 4);
    __half* d0 = z + ((size_t)b * SS + zr0) * EE + (sg0 & 15) * 64;
    __half* d1 = z + ((size_t)b * SS + zr1) * EE + (sg1 & 15) * 64;
#pragma unroll
    for (int nt = 0; nt < 8; nt++) {
        int col = nt * 8 + 2 * cq;
        *(uint32_t*)(d0 + col) = h2pack(o[nt][0] * inv0, o[nt][1] * inv0);
        *(uint32_t*)(d1 + col) = h2pack(o[nt][2] * inv1, o[nt][3] * inv1);
    }
}

// ---------------------------------------------------------------------------
extern "C" void kernel_launch(void* const* d_in, const int* in_sizes, int n_in,
                              void* d_out, int out_size)
{
    (void)in_sizes; (void)n_in; (void)out_size;
    const float* x    = (const float*)d_in[0];
    const float* Wqkv = (const float*)d_in[1];
    const float* Wout = (const float*)d_in[2];
    float* out = (float*)d_out;

    void *p_qkv, *p_z, *p_xh, *p_wqt, *p_wot;
    cudaGetSymbolAddress(&p_qkv, g_qkv);
    cudaGetSymbolAddress(&p_z, g_z);
    cudaGetSymbolAddress(&p_xh, g_xh);
    cudaGetSymbolAddress(&p_wqt, g_wqt);
    cudaGetSymbolAddress(&p_wot, g_wot);
    __half* qkv = (__half*)p_qkv;
    __half* zb  = (__half*)p_z;
    __half* xh  = (__half*)p_xh;
    __half* wqt = (__half*)p_wqt;
    __half* wot = (__half*)p_wot;

    const int SMEM_G = 2 * 2 * 128 * PITCH * 2;  // 73728
    const int SMEM_A = 2 * 2 * 64 * PITCH * 2;   // 36864
    cudaFuncSetAttribute(hgemm_kernel,
                         cudaFuncAttributeMaxDynamicSharedMemorySize, SMEM_G);
    cudaFuncSetAttribute(attn_kernel,
                         cudaFuncAttributeMaxDynamicSharedMemorySize, SMEM_A);

    dim3 blk(256);
    // 0) Merged pre-pass: x -> fp16; both weights -> fp16 transposed [N,K]
    prepass_kernel<<<NBX + NBQ + NBO, blk>>>(x, Wqkv, Wout, xh, wqt, wot);
    // 1) QKV projection -> fp16 qkv
    hgemm_kernel<<<dim3(QKVN / 128, MROWS / 128), blk, SMEM_G>>>(
        xh, wqt, qkv, MROWS, QKVN, EE, 1);
    // 2) Attention -> fp16 scrambled z
    attn_kernel<<<dim3(BB * HH, SS / 128), blk, SMEM_A>>>(qkv, zb);
    // 3) Output projection -> fp32 out
    hgemm_kernel<<<dim3(EE / 128, MROWS / 128), blk, SMEM_G>>>(
        zb, wot, out, MROWS, EE, EE, 0);
}

// round 16
// speedup vs baseline: 1.5142x; 1.0295x over previous
#include <cuda_runtime.h>
#include <cuda_fp16.h>
#include <cstdint>

// Problem constants
#define BB 4
#define SS 2048
#define EE 1024
#define HH 16
#define DD 64
#define MROWS (BB * SS)      // 8192
#define QKVN  (3 * HH * DD)  // 3072
#define PITCH 72             // SMEM row pitch in halves (144B, conflict-free)

// Scratch (allocation-free rule: __device__ globals)
__device__ __half g_qkv[(size_t)MROWS * QKVN];  // 48 MB
__device__ __half g_z[(size_t)MROWS * EE];      // 16 MB (scrambled z)
__device__ __half g_xh[(size_t)MROWS * EE];     // 16 MB (x fp16)
__device__ __half g_wqt[(size_t)QKVN * EE];     //  6 MB (W_qkv^T fp16 [N,K])
__device__ __half g_wot[(size_t)EE * EE];       //  2 MB (W_out^T fp16 [N,K])

__device__ __forceinline__ uint32_t h2pack(float lo, float hi) {
    uint32_t r;
    asm("cvt.rn.f16x2.f32 %0, %1, %2;" : "=r"(r) : "f"(hi), "f"(lo));
    return r;
}
__device__ __forceinline__ float ex2(float x) {
    float y;
    asm("ex2.approx.f32 %0, %1;" : "=f"(y) : "f"(x));
    return y;
}
__device__ __forceinline__ uint32_t ex2h2(uint32_t x) {
    uint32_t y;
    asm("ex2.approx.f16x2 %0, %1;" : "=r"(y) : "r"(x));
    return y;
}
__device__ __forceinline__ uint32_t sptr(const void* p) {
    return (uint32_t)__cvta_generic_to_shared(p);
}
__device__ __forceinline__ void cp16(void* dst, const void* src) {
    uint32_t d = sptr(dst);
    asm volatile("cp.async.cg.shared.global [%0], [%1], 16;" :: "r"(d), "l"(src));
}
#define CP_COMMIT() asm volatile("cp.async.commit_group;")
#define CP_WAIT0()  asm volatile("cp.async.wait_group 0;")

__device__ __forceinline__ void ldsm4(uint32_t r[4], uint32_t addr) {
    asm volatile("ldmatrix.sync.aligned.m8n8.x4.shared.b16 {%0,%1,%2,%3}, [%4];"
                 : "=r"(r[0]), "=r"(r[1]), "=r"(r[2]), "=r"(r[3]) : "r"(addr));
}
__device__ __forceinline__ void ldsm4t(uint32_t r[4], uint32_t addr) {
    asm volatile("ldmatrix.sync.aligned.m8n8.x4.trans.shared.b16 {%0,%1,%2,%3}, [%4];"
                 : "=r"(r[0]), "=r"(r[1]), "=r"(r[2]), "=r"(r[3]) : "r"(addr));
}
__device__ __forceinline__ void ldsm2t(uint32_t& r0, uint32_t& r1,
                                       uint32_t addr) {
    asm volatile("ldmatrix.sync.aligned.m8n8.x2.trans.shared.b16 {%0,%1}, [%2];"
                 : "=r"(r0), "=r"(r1) : "r"(addr));
}
__device__ __forceinline__ void mma16816(float d[4], const uint32_t a[4],
                                         uint32_t b0, uint32_t b1) {
    asm volatile(
        "mma.sync.aligned.m16n8k16.row.col.f32.f16.f16.f32 "
        "{%0,%1,%2,%3}, {%4,%5,%6,%7}, {%8,%9}, {%0,%1,%2,%3};\n"
        : "+f"(d[0]), "+f"(d[1]), "+f"(d[2]), "+f"(d[3])
        : "r"(a[0]), "r"(a[1]), "r"(a[2]), "r"(a[3]), "r"(b0), "r"(b1));
}

// ---------------------------------------------------------------------------
// Merged pre-pass (exact R15 version)
// ---------------------------------------------------------------------------
#define NBX (MROWS * EE / 4 / 256)      // 8192
#define NBQ ((QKVN / 32) * (EE / 32))   // 3072
#define NBO ((EE / 32) * (EE / 32))     // 1024

__device__ __forceinline__ void transpose_tile(
    const float* __restrict__ src, __half* __restrict__ dst,
    int R, int C, int bx, int by, int tx, int ty, float* t /*[32][33]*/)
{
    int x = bx * 32 + tx;
#pragma unroll
    for (int i = 0; i < 4; i++) {
        int y = by * 32 + ty + i * 8;
        t[(ty + i * 8) * 33 + tx] = src[(size_t)y * C + x];
    }
    __syncthreads();
    int xo = by * 32 + tx;
#pragma unroll
    for (int i = 0; i < 4; i++) {
        int yo = bx * 32 + ty + i * 8;
        dst[(size_t)yo * R + xo] = __float2half_rn(t[tx * 33 + ty + i * 8]);
    }
}

__global__ __launch_bounds__(256) void prepass_kernel(
    const float* __restrict__ x, const float* __restrict__ Wqkv,
    const float* __restrict__ Wout, __half* __restrict__ xh,
    __half* __restrict__ wqt, __half* __restrict__ wot)
{
    __shared__ float t[32 * 33];
    const int blk = blockIdx.x;
    const int tid = threadIdx.x;
    const int tx = tid & 31;
    const int ty = tid >> 5;

    if (blk < NBX) {
        int i = blk * 256 + tid;
        float4 v = ((const float4*)x)[i];
        uint2 o;
        o.x = h2pack(v.x, v.y);
        o.y = h2pack(v.z, v.w);
        ((uint2*)xh)[i] = o;
    } else if (blk < NBX + NBQ) {
        int idx = blk - NBX;
        int bx = idx % (QKVN / 32);
        int by = idx / (QKVN / 32);
        transpose_tile(Wqkv, wqt, EE, QKVN, bx, by, tx, ty, t);
    } else {
        int idx = blk - NBX - NBQ;
        int bx = idx % (EE / 32);
        int by = idx / (EE / 32);
        transpose_tile(Wout, wot, EE, EE, bx, by, tx, ty, t);
    }
}

// ---------------------------------------------------------------------------
// fp16 tensor-core GEMM (exact R10/R11 version): C[M,N] = A[M,K] @ Bt[N,K]^T.
// ---------------------------------------------------------------------------
__global__ __launch_bounds__(256, 2) void hgemm_kernel(
    const __half* __restrict__ A, const __half* __restrict__ Bt,
    void* __restrict__ Cv, int M, int N, int K, int half_out)
{
    extern __shared__ __half smh[];
    const int stA = 128 * PITCH;
    __half* Asm = smh;
    __half* Bsm = smh + 2 * stA;

    const int tid = threadIdx.x;
    const int lane = tid & 31;
    const int wid = tid >> 5;
    const int wm = wid & 3;
    const int wn = wid >> 2;
    const int r = lane >> 2;
    const int cq = lane & 3;
    const int m0 = blockIdx.y * 128;
    const int n0 = blockIdx.x * 128;

    const int a_row_l = ((lane >> 3) & 1) * 8 + (lane & 7);
    const int a_col_l = ((lane >> 4) & 1) * 8;
    const int b_row_l = lane & 7;
    const int b_col_l = (lane >> 3) * 8;

    float acc[2][8][4];
#pragma unroll
    for (int i = 0; i < 2; i++)
#pragma unroll
        for (int j = 0; j < 8; j++)
#pragma unroll
            for (int q = 0; q < 4; q++) acc[i][j][q] = 0.f;

    auto cp_chunk = [&](int buf, int k0, int j) {
        int f = (j & 3) * 256 + tid;
        int row = f >> 3;
        int c = (f & 7) * 8;
        if (j < 4)
            cp16(Asm + buf * stA + row * PITCH + c,
                 A + (size_t)(m0 + row) * K + k0 + c);
        else
            cp16(Bsm + buf * stA + row * PITCH + c,
                 Bt + (size_t)(n0 + row) * K + k0 + c);
    };
    auto load_tile = [&](int buf, int k0) {
#pragma unroll
        for (int j = 0; j < 8; j++) cp_chunk(buf, k0, j);
        CP_COMMIT();
    };

    const int ntiles = K / 64;
    load_tile(0, 0);

    for (int it = 0; it < ntiles; it++) {
        const int cur = it & 1;
        CP_WAIT0();
        __syncthreads();
        const bool pf = (it + 1 < ntiles);
        const int nk0 = (it + 1) * 64;

        __half* Ab = Asm + cur * stA;
        __half* Bb = Bsm + cur * stA;

#pragma unroll
        for (int ksp = 0; ksp < 2; ksp++) {
            uint32_t af[2][2][4];
#pragma unroll
            for (int im = 0; im < 2; im++)
#pragma unroll
                for (int sub = 0; sub < 2; sub++)
                    ldsm4(af[im][sub],
                          sptr(Ab + (wm * 32 + im * 16 + a_row_l) * PITCH +
                               ksp * 32 + sub * 16 + a_col_l));

#pragma unroll
            for (int nh = 0; nh < 2; nh++) {
                uint32_t bf[4][4];
#pragma unroll
                for (int g = 0; g < 4; g++)
                    ldsm4(bf[g],
                          sptr(Bb + (wn * 64 + (nh * 4 + g) * 8 + b_row_l) * PITCH +
                               ksp * 32 + b_col_l));

                if (pf) {
                    cp_chunk(cur ^ 1, nk0, 2 * (ksp * 2 + nh));
                    cp_chunk(cur ^ 1, nk0, 2 * (ksp * 2 + nh) + 1);
                }

#pragma unroll
                for (int sub = 0; sub < 2; sub++)
#pragma unroll
                    for (int im = 0; im < 2; im++)
#pragma unroll
                        for (int g = 0; g < 4; g++)
                            mma16816(acc[im][nh * 4 + g], af[im][sub],
                                     bf[g][2 * sub], bf[g][2 * sub + 1]);
            }
        }
        CP_COMMIT();
    }

    if (half_out) {
        __half* C = (__half*)Cv;
#pragma unroll
        for (int im = 0; im < 2; im++)
#pragma unroll
            for (int nt = 0; nt < 8; nt++) {
                int row = m0 + wm * 32 + im * 16 + r;
                int col = n0 + wn * 64 + nt * 8 + 2 * cq;
                *(uint32_t*)(C + (size_t)row * N + col) =
                    h2pack(acc[im][nt][0], acc[im][nt][1]);
                *(uint32_t*)(C + (size_t)(row + 8) * N + col) =
                    h2pack(acc[im][nt][2], acc[im][nt][3]);
            }
    } else {
        float* C = (float*)Cv;
#pragma unroll
        for (int im = 0; im < 2; im++)
#pragma unroll
            for (int nt = 0; nt < 8; nt++) {
                int row = m0 + wm * 32 + im * 16 + r;
                int col = n0 + wn * 64 + nt * 8 + 2 * cq;
                *(float2*)(C + (size_t)row * N + col) =
                    make_float2(acc[im][nt][0], acc[im][nt][1]);
                *(float2*)(C + (size_t)(row + 8) * N + col) =
                    make_float2(acc[im][nt][2], acc[im][nt][3]);
            }
    }
}

// ---------------------------------------------------------------------------
// Flash attention v2: 128 threads (4 warps), 32 q-rows/warp (2 m16-tiles)
// -> each K/V fragment feeds 2x MMAs (ldsm:MMA 36:136), halving SMEM reads.
// fp16 MMA, f16x2 ex2 softmax with online max + rescale-skip, l via
// ones-column MMA. 2-stage cp.async. grid (B*H, S/128): 1024 CTAs.
// Writes z fp16 in scrambled layout: z[b, h*128+s/16, (s%16)*64+d]
// ---------------------------------------------------------------------------
__global__ __launch_bounds__(128, 2) void attn_kernel(
    const __half* __restrict__ qkv, __half* __restrict__ z)
{
    extern __shared__ __half sma[];
    const int stK = 64 * PITCH;
    __half* Ksm = sma;
    __half* Vsm = sma + 2 * stK;

    const int bh = blockIdx.x;
    const int b = bh >> 4;
    const int h = bh & 15;
    const int s0 = blockIdx.y * 128;
    const int tid = threadIdx.x;
    const int lane = tid & 31;
    const int warp = tid >> 5;      // 0..3, owns q-rows [warp*32, warp*32+32)
    const int r = lane >> 2;
    const int cq = lane & 3;

    const int k_row_l = ((lane >> 4) & 1) * 8 + (lane & 7);
    const int k_col_l = ((lane >> 3) & 1) * 8;
    const int v_row_l = ((lane >> 3) & 1) * 8 + (lane & 7);
    const int v_col_l = ((lane >> 4) & 1) * 8;

    const __half* base = qkv + (size_t)b * SS * QKVN + h * DD;

    const float QSCALE = 0.125f * 1.44269504088896340736f;
    uint32_t qa[2][4][4];           // [m-tile][ks][frag]
#pragma unroll
    for (int mt = 0; mt < 2; mt++) {
        const int row0 = s0 + warp * 32 + mt * 16 + r;
        const __half* q0 = base + (size_t)row0 * QKVN;
        const __half* q1 = base + (size_t)(row0 + 8) * QKVN;
#pragma unroll
        for (int ks = 0; ks < 4; ks++) {
            float2 f0 = __half22float2(*(const __half2*)(q0 + 16 * ks + 2 * cq));
            float2 f1 = __half22float2(*(const __half2*)(q1 + 16 * ks + 2 * cq));
            float2 f2 = __half22float2(*(const __half2*)(q0 + 16 * ks + 8 + 2 * cq));
            float2 f3 = __half22float2(*(const __half2*)(q1 + 16 * ks + 8 + 2 * cq));
            qa[mt][ks][0] = h2pack(f0.x * QSCALE, f0.y * QSCALE);
            qa[mt][ks][1] = h2pack(f1.x * QSCALE, f1.y * QSCALE);
            qa[mt][ks][2] = h2pack(f2.x * QSCALE, f2.y * QSCALE);
            qa[mt][ks][3] = h2pack(f3.x * QSCALE, f3.y * QSCALE);
        }
    }

    // Ones column for l row-sums: V col 64 = 1.0, cols 65-71 = 0 (both bufs).
    {
        int buf = tid >> 6, row = tid & 63;  // 128 threads cover 2x64 rows
        uint4 ones = make_uint4(0x00003C00u, 0u, 0u, 0u);
        *(uint4*)(Vsm + buf * stK + row * PITCH + 64) = ones;
    }

    auto load_kv = [&](int buf, int kt) {
#pragma unroll
        for (int i = 0; i < 8; i++) {
            int f = i * 128 + tid;          // 0..1023
            int isv = f >> 9;
            int g = f & 511;
            int t = g >> 3;
            int c = (g & 7) * 8;
            const __half* src = base + (size_t)(kt + t) * QKVN +
                                (isv ? 2048 : 1024) + c;
            __half* dst = (isv ? Vsm : Ksm) + buf * stK + t * PITCH + c;
            cp16(dst, src);
        }
        CP_COMMIT();
    };

    // o[mt][0..7]: output cols; o[mt][8]: ones accumulator (l in [0],[2])
    float o[2][9][4];
#pragma unroll
    for (int mt = 0; mt < 2; mt++)
#pragma unroll
        for (int nt = 0; nt < 9; nt++)
#pragma unroll
            for (int q = 0; q < 4; q++) o[mt][nt][q] = 0.f;
    // running maxes: [mt*2] = row r, [mt*2+1] = row r+8
    float mrow[4] = {-1e30f, -1e30f, -1e30f, -1e30f};

    load_kv(0, 0);

    for (int it = 0; it < SS / 64; it++) {
        const int cur = it & 1;
        CP_WAIT0();
        __syncthreads();
        if (it + 1 < SS / 64) load_kv(cur ^ 1, (it + 1) * 64);

        __half* Kb = Ksm + cur * stK;
        __half* Vb = Vsm + cur * stK;

        // S = Q @ K^T for both m-tiles; each K fragment used 4x
        float s[2][8][4];
#pragma unroll
        for (int mt = 0; mt < 2; mt++)
#pragma unroll
            for (int nt = 0; nt < 8; nt++)
#pragma unroll
                for (int q = 0; q < 4; q++) s[mt][nt][q] = 0.f;
#pragma unroll
        for (int ks = 0; ks < 4; ks++) {
#pragma unroll
            for (int ntp = 0; ntp < 4; ntp++) {
                uint32_t kb[4];
                uint32_t kd = sptr(Kb + (ntp * 16 + k_row_l) * PITCH +
                                   ks * 16 + k_col_l);
                ldsm4(kb, kd);
#pragma unroll
                for (int mt = 0; mt < 2; mt++) {
                    mma16816(s[mt][2 * ntp],     qa[mt][ks], kb[0], kb[1]);
                    mma16816(s[mt][2 * ntp + 1], qa[mt][ks], kb[2], kb[3]);
                }
            }
        }

        // Online max (base-2 domain), 4 rows per thread-quad
        float mn[4];
#pragma unroll
        for (int mt = 0; mt < 2; mt++) {
            float m0 = -1e30f, m1 = -1e30f;
#pragma unroll
            for (int nt = 0; nt < 8; nt++) {
                m0 = fmaxf(m0, fmaxf(s[mt][nt][0], s[mt][nt][1]));
                m1 = fmaxf(m1, fmaxf(s[mt][nt][2], s[mt][nt][3]));
            }
            m0 = fmaxf(m0, __shfl_xor_sync(0xffffffffu, m0, 1));
            m0 = fmaxf(m0, __shfl_xor_sync(0xffffffffu, m0, 2));
            m1 = fmaxf(m1, __shfl_xor_sync(0xffffffffu, m1, 1));
            m1 = fmaxf(m1, __shfl_xor_sync(0xffffffffu, m1, 2));
            mn[2 * mt]     = fmaxf(mrow[2 * mt], m0);
            mn[2 * mt + 1] = fmaxf(mrow[2 * mt + 1], m1);
        }

        // Rescale only if some row max changed anywhere in the warp
        bool stable = (mn[0] == mrow[0]) && (mn[1] == mrow[1]) &&
                      (mn[2] == mrow[2]) && (mn[3] == mrow[3]);
        if (!__all_sync(0xffffffffu, stable)) {
#pragma unroll
            for (int mt = 0; mt < 2; mt++) {
                float c0 = ex2(mrow[2 * mt] - mn[2 * mt]);
                float c1 = ex2(mrow[2 * mt + 1] - mn[2 * mt + 1]);
#pragma unroll
                for (int nt = 0; nt < 9; nt++) {
                    o[mt][nt][0] *= c0;
                    o[mt][nt][1] *= c0;
                    o[mt][nt][2] *= c1;
                    o[mt][nt][3] *= c1;
                }
            }
        }
#pragma unroll
        for (int j = 0; j < 4; j++) mrow[j] = mn[j];

        // P = exp2(s - mn) in f16x2 (A-fragment layout), per m-tile
        uint32_t pa[2][4][4];
#pragma unroll
        for (int mt = 0; mt < 2; mt++) {
            float mn0 = mn[2 * mt], mn1 = mn[2 * mt + 1];
#pragma unroll
            for (int ks = 0; ks < 4; ks++) {
                pa[mt][ks][0] = ex2h2(h2pack(s[mt][2 * ks][0] - mn0,
                                             s[mt][2 * ks][1] - mn0));
                pa[mt][ks][1] = ex2h2(h2pack(s[mt][2 * ks][2] - mn1,
                                             s[mt][2 * ks][3] - mn1));
                pa[mt][ks][2] = ex2h2(h2pack(s[mt][2 * ks + 1][0] - mn0,
                                             s[mt][2 * ks + 1][1] - mn0));
                pa[mt][ks][3] = ex2h2(h2pack(s[mt][2 * ks + 1][2] - mn1,
                                             s[mt][2 * ks + 1][3] - mn1));
            }
        }

        // O += P @ V; each V fragment used 2x (+ ones column for l)
#pragma unroll
        for (int ks = 0; ks < 4; ks++) {
            uint32_t w0, w1;
            ldsm2t(w0, w1, sptr(Vb + (ks * 16 + (lane & 15)) * PITCH + 64));
            mma16816(o[0][8], pa[0][ks], w0, w1);
            mma16816(o[1][8], pa[1][ks], w0, w1);
#pragma unroll
            for (int dp = 0; dp < 4; dp++) {
                uint32_t vb[4];
                uint32_t vd = sptr(Vb + (ks * 16 + v_row_l) * PITCH +
                                   dp * 16 + v_col_l);
                ldsm4t(vb, vd);
#pragma unroll
                for (int mt = 0; mt < 2; mt++) {
                    mma16816(o[mt][2 * dp],     pa[mt][ks], vb[0], vb[1]);
                    mma16816(o[mt][2 * dp + 1], pa[mt][ks], vb[2], vb[3]);
                }
            }
        }
    }

    // Epilogue per m-tile: l in the cq==0 lane of each quad (col 64)
#pragma unroll
    for (int mt = 0; mt < 2; mt++) {
        float l0 = __shfl_sync(0xffffffffu, o[mt][8][0], lane & ~3);
        float l1 = __shfl_sync(0xffffffffu, o[mt][8][2], lane & ~3);
        float inv0 = 1.f / l0;
        float inv1 = 1.f / l1;
        int sg0 = s0 + warp * 32 + mt * 16 + r;
        int sg1 = sg0 + 8;
        int zr0 = h * 128 + (sg0 >> 4);
        int zr1 = h * 128 + (sg1 >> 4);
        __half* d0 = z + ((size_t)b * SS + zr0) * EE + (sg0 & 15) * 64;
        __half* d1 = z + ((size_t)b * SS + zr1) * EE + (sg1 & 15) * 64;
#pragma unroll
        for (int nt = 0; nt < 8; nt++) {
            int col = nt * 8 + 2 * cq;
            *(uint32_t*)(d0 + col) = h2pack(o[mt][nt][0] * inv0,
                                            o[mt][nt][1] * inv0);
            *(uint32_t*)(d1 + col) = h2pack(o[mt][nt][2] * inv1,
                                            o[mt][nt][3] * inv1);
        }
    }
}

// ---------------------------------------------------------------------------
extern "C" void kernel_launch(void* const* d_in, const int* in_sizes, int n_in,
                              void* d_out, int out_size)
{
    (void)in_sizes; (void)n_in; (void)out_size;
    const float* x    = (const float*)d_in[0];
    const float* Wqkv = (const float*)d_in[1];
    const float* Wout = (const float*)d_in[2];
    float* out = (float*)d_out;

    void *p_qkv, *p_z, *p_xh, *p_wqt, *p_wot;
    cudaGetSymbolAddress(&p_qkv, g_qkv);
    cudaGetSymbolAddress(&p_z, g_z);
    cudaGetSymbolAddress(&p_xh, g_xh);
    cudaGetSymbolAddress(&p_wqt, g_wqt);
    cudaGetSymbolAddress(&p_wot, g_wot);
    __half* qkv = (__half*)p_qkv;
    __half* zb  = (__half*)p_z;
    __half* xh  = (__half*)p_xh;
    __half* wqt = (__half*)p_wqt;
    __half* wot = (__half*)p_wot;

    const int SMEM_G = 2 * 2 * 128 * PITCH * 2;  // 73728
    const int SMEM_A = 2 * 2 * 64 * PITCH * 2;   // 36864
    cudaFuncSetAttribute(hgemm_kernel,
                         cudaFuncAttributeMaxDynamicSharedMemorySize, SMEM_G);
    cudaFuncSetAttribute(attn_kernel,
                         cudaFuncAttributeMaxDynamicSharedMemorySize, SMEM_A);

    dim3 blk(256);
    // 0) Merged pre-pass: x -> fp16; both weights -> fp16 transposed [N,K]
    prepass_kernel<<<NBX + NBQ + NBO, blk>>>(x, Wqkv, Wout, xh, wqt, wot);
    // 1) QKV projection -> fp16 qkv
    hgemm_kernel<<<dim3(QKVN / 128, MROWS / 128), blk, SMEM_G>>>(
        xh, wqt, qkv, MROWS, QKVN, EE, 1);
    // 2) Attention -> fp16 scrambled z (128-thread CTAs, 32 q-rows/warp)
    attn_kernel<<<dim3(BB * HH, SS / 128), 128, SMEM_A>>>(qkv, zb);
    // 3) Output projection -> fp32 out
    hgemm_kernel<<<dim3(EE / 128, MROWS / 128), blk, SMEM_G>>>(
        zb, wot, out, MROWS, EE, EE, 0);
}